// round 9
// baseline (speedup 1.0000x reference)
#include <cuda_runtime.h>
#include <math.h>

// ---------------------------------------------------------------------------
// Static device scratch (zero-initialized at module load; halos stay zero).
// ---------------------------------------------------------------------------
__device__ float g_pad_in[1882384];   // [2][1][98][98][98]
__device__ float g_act0[8000000];     // [2][32][50][50][50]
__device__ float g_act1[2249728];     // [2][64][26][26][26]
__device__ float g_act2[702464];      // [2][128][14][14][14]
__device__ float g_act3[262144];      // [2][256][8][8][8]
__device__ float g_act4[128000];      // [2][512][5][5][5]
__device__ float g_act5[1024];        // [2][512] flat
__device__ float g_accum[7077888];    // conv split-K accumulator / l5 xcol scratch
__device__ float g_z[256];            // [2][128]
__device__ float g_deltas[3066];      // [2][3][511]
__device__ float g_knots[3072];       // [2][3][512]
__device__ float g_feats[98304];      // [2][3][512][32]
__device__ float g_ltab[18432];       // [2][3][96][32]

#define P3 884736       // 96^3
#define OUT_MU_OFF 1769472

typedef unsigned long long ull;

__device__ __forceinline__ ull pk2(float x, float y) {
    ull r; asm("mov.b64 %0, {%1,%2};" : "=l"(r) : "f"(x), "f"(y)); return r;
}
__device__ __forceinline__ void upk2(ull v, float& x, float& y) {
    asm("mov.b64 {%0,%1}, %2;" : "=f"(x), "=f"(y) : "l"(v));
}
__device__ __forceinline__ ull fma2_(ull a, ull b, ull c) {
    ull d; asm("fma.rn.f32x2 %0, %1, %2, %3;" : "=l"(d) : "l"(a), "l"(b), "l"(c)); return d;
}

// ---------------------------------------------------------------------------
// Pad occ [2,1,96,96,96] into [2,1,98,98,98] (halo already zero).
// ---------------------------------------------------------------------------
__global__ void pad_kernel(const float* __restrict__ occ) {
    int idx = blockIdx.x * 256 + threadIdx.x;
    if (idx >= 2 * P3) return;
    int b = idx / P3;
    int r = idx - b * P3;
    int d = r / 9216;
    int h = (r / 96) % 96;
    int w = r % 96;
    g_pad_in[b * 941192 + (d + 1) * 9604 + (h + 1) * 98 + (w + 1)] = occ[idx];
}

__global__ void zero_kernel(float* __restrict__ p, int n) {
    int i = blockIdx.x * 256 + threadIdx.x;
    if (i < n) p[i] = 0.f;
}

// ---------------------------------------------------------------------------
// Implicit-GEMM conv: C[co, n] = sum_k W[co,k] * col[k,n]
// 64x64x16 tiles, 256 threads, 4x4 micro-tile, packed f32x2 FMA.
// A stored in smem PRE-DUPLICATED (Ad[k][2m]=Ad[k][2m+1]=W[m,k]) so the
// mainloop is 3x LDS.128 + 8x FFMA2 per kk — FMA-bound instead of L1-bound.
// ---------------------------------------------------------------------------
__global__ __launch_bounds__(256) void conv_gemm(
    const float* __restrict__ inp, const float* __restrict__ wgt,
    float* __restrict__ accum, const float* __restrict__ bias,
    float* __restrict__ fout,
    int Cin, int Sp, int Sout, int Cout, int K, int N, int Npad, int Kchunk,
    int Spn)
{
    __shared__ __align__(16) float Ad[2][16][136];  // duplicated A, 128 used/row
    __shared__ __align__(16) float Bs[2][16][68];
    __shared__ int baseN[64];
    int tid = threadIdx.x;
    int bx = blockIdx.x, by = blockIdx.y;
    int Sp2 = Sp * Sp, Sp3 = Sp2 * Sp;

    if (tid < 64) {
        int n = bx * 64 + tid;
        int base = 0;
        if (n < N) {
            int s2 = Sout * Sout, s3 = s2 * Sout;
            int b = n / s3; int rem = n - b * s3;
            int od = rem / s2; rem -= od * s2;
            int oh = rem / Sout; int ow = rem - oh * Sout;
            base = b * Cin * Sp3 + 2 * od * Sp2 + 2 * oh * Sp + 2 * ow;
        }
        baseN[tid] = base;
    }
    __syncthreads();

    int tx4 = (tid & 15) * 4;
    int ty4 = (tid >> 4) * 4;
    int m_ld = tid >> 2;          // A load: row (co)
    int kq   = (tid & 3) * 4;     // A load: 4 consecutive k
    int kk_b = tid >> 4;          // B load: k row
    int nb4  = (tid & 15) * 4;    // B load: 4 n cols
    int k0 = blockIdx.z * Kchunk;

    int coA = by * 64 + m_ld;
    bool mval = (coA < Cout);
    const float* wrowp = wgt + (long long)coA * K + k0 + kq;
    int bb0 = baseN[nb4], bb1 = baseN[nb4 + 1], bb2 = baseN[nb4 + 2], bb3 = baseN[nb4 + 3];

    ull c2[4][2];   // [i][jp]: rows i, packed n-pairs jp
    #pragma unroll
    for (int i = 0; i < 4; i++) { c2[i][0] = 0ull; c2[i][1] = 0ull; }

    int nst = Kchunk >> 4;
    float ar[4], br[4];

    // prologue: stage 0
    {
        #pragma unroll
        for (int i = 0; i < 4; i++) ar[i] = mval ? wrowp[i] : 0.f;
        int kg = k0 + kk_b;
        int ci = kg >> 6, rr = kg & 63;
        int off = ci * Sp3 + (rr >> 4) * Sp2 + ((rr >> 2) & 3) * Sp + (rr & 3);
        br[0] = inp[bb0 + off]; br[1] = inp[bb1 + off];
        br[2] = inp[bb2 + off]; br[3] = inp[bb3 + off];
        #pragma unroll
        for (int i = 0; i < 4; i++)
            *(float2*)&Ad[0][kq + i][2 * m_ld] = make_float2(ar[i], ar[i]);
        *(float4*)&Bs[0][kk_b][nb4] = make_float4(br[0], br[1], br[2], br[3]);
    }
    __syncthreads();

    for (int t = 0; t < nst; t++) {
        int cur = t & 1;
        bool more = (t + 1 < nst);
        if (more) {
            const float* wp = wrowp + (t + 1) * 16;
            #pragma unroll
            for (int i = 0; i < 4; i++) ar[i] = mval ? wp[i] : 0.f;
            int kg = k0 + (t + 1) * 16 + kk_b;
            int ci = kg >> 6, rr = kg & 63;
            int off = ci * Sp3 + (rr >> 4) * Sp2 + ((rr >> 2) & 3) * Sp + (rr & 3);
            br[0] = inp[bb0 + off]; br[1] = inp[bb1 + off];
            br[2] = inp[bb2 + off]; br[3] = inp[bb3 + off];
        }
        #pragma unroll
        for (int kk = 0; kk < 16; kk++) {
            double2 bq = *(const double2*)&Bs[cur][kk][tx4];        // (n0,n1),(n2,n3)
            double2 a01 = *(const double2*)&Ad[cur][kk][2 * ty4];   // (a0,a0),(a1,a1)
            double2 a23 = *(const double2*)&Ad[cur][kk][2 * ty4 + 4];
            ull bv0 = __double_as_longlong(bq.x);
            ull bv1 = __double_as_longlong(bq.y);
            ull ad0 = __double_as_longlong(a01.x);
            ull ad1 = __double_as_longlong(a01.y);
            ull ad2 = __double_as_longlong(a23.x);
            ull ad3 = __double_as_longlong(a23.y);
            c2[0][0] = fma2_(ad0, bv0, c2[0][0]);
            c2[0][1] = fma2_(ad0, bv1, c2[0][1]);
            c2[1][0] = fma2_(ad1, bv0, c2[1][0]);
            c2[1][1] = fma2_(ad1, bv1, c2[1][1]);
            c2[2][0] = fma2_(ad2, bv0, c2[2][0]);
            c2[2][1] = fma2_(ad2, bv1, c2[2][1]);
            c2[3][0] = fma2_(ad3, bv0, c2[3][0]);
            c2[3][1] = fma2_(ad3, bv1, c2[3][1]);
        }
        if (more) {
            int nx = cur ^ 1;
            #pragma unroll
            for (int i = 0; i < 4; i++)
                *(float2*)&Ad[nx][kq + i][2 * m_ld] = make_float2(ar[i], ar[i]);
            *(float4*)&Bs[nx][kk_b][nb4] = make_float4(br[0], br[1], br[2], br[3]);
        }
        __syncthreads();
    }

    float c[4][4];
    #pragma unroll
    for (int i = 0; i < 4; i++) {
        upk2(c2[i][0], c[i][0], c[i][1]);
        upk2(c2[i][1], c[i][2], c[i][3]);
    }

    if (gridDim.z == 1) {
        // fused bias + ReLU + scatter to padded output
        int Spn2 = Spn * Spn;
        int s2 = Sout * Sout, s3 = s2 * Sout;
        #pragma unroll
        for (int i = 0; i < 4; i++) {
            int co = by * 64 + ty4 + i;
            if (co >= Cout) continue;
            float bv = bias[co];
            #pragma unroll
            for (int j = 0; j < 4; j++) {
                int n = bx * 64 + tx4 + j;
                if (n < N) {
                    int b = n / s3; int rem = n - b * s3;
                    int od = rem / s2; rem -= od * s2;
                    int oh = rem / Sout; int ow = rem - oh * Sout;
                    float v = fmaxf(c[i][j] + bv, 0.f);
                    fout[((b * Cout + co) * Spn + od + 1) * Spn2 + (oh + 1) * Spn + (ow + 1)] = v;
                }
            }
        }
    } else {
        #pragma unroll
        for (int i = 0; i < 4; i++) {
            int co = by * 64 + ty4 + i;
            if (co >= Cout) continue;
            #pragma unroll
            for (int j = 0; j < 4; j++) {
                int n = bx * 64 + tx4 + j;
                if (n < N) atomicAdd(&accum[co * Npad + n], c[i][j]);
            }
        }
    }
}

// ---------------------------------------------------------------------------
// Epilogue for split-K layers: bias + ReLU + scatter into next padded buffer.
// ---------------------------------------------------------------------------
__global__ void conv_epilogue(
    const float* __restrict__ accum, const float* __restrict__ bias,
    float* __restrict__ outp,
    int Cout, int Sout, int Spn, int N, int Npad)
{
    int idx = blockIdx.x * 256 + threadIdx.x;
    if (idx >= Cout * N) return;
    int m = idx / N;
    int n = idx - m * N;
    float v = fmaxf(accum[m * Npad + n] + bias[m], 0.f);
    int s2 = Sout * Sout, s3 = s2 * Sout;
    int b = n / s3; int rem = n - b * s3;
    int od = rem / s2; rem -= od * s2;
    int oh = rem / Sout; int ow = rem - oh * Sout;
    int Spn2 = Spn * Spn;
    outp[((b * Cout + m) * Spn + od + 1) * Spn2 + (oh + 1) * Spn + (ow + 1)] = v;
}

// ---------------------------------------------------------------------------
// Layer 5: gather col vector (coalesced scratch), then matvec over 32768.
// ---------------------------------------------------------------------------
__global__ void l5_xcol() {
    int idx = blockIdx.x * 256 + threadIdx.x;   // 2*32768
    if (idx >= 65536) return;
    int b = idx >> 15;
    int k = idx & 32767;
    int ci = k >> 6, rr = k & 63;
    int off = ci * 125 + (rr >> 4) * 25 + ((rr >> 2) & 3) * 5 + (rr & 3);
    g_accum[idx] = g_act4[b * 64000 + off];
}

__global__ __launch_bounds__(256) void l5_matvec(
    const float* __restrict__ wgt, const float* __restrict__ bias)
{
    int co = blockIdx.x;
    int tid = threadIdx.x;
    const float* w = wgt + (long long)co * 32768;
    float s0 = 0.f, s1 = 0.f;
    for (int k = tid; k < 32768; k += 256) {
        float wv = w[k];
        s0 += wv * g_accum[k];
        s1 += wv * g_accum[32768 + k];
    }
    __shared__ float r0[256], r1[256];
    r0[tid] = s0; r1[tid] = s1;
    __syncthreads();
    for (int o = 128; o > 0; o >>= 1) {
        if (tid < o) { r0[tid] += r0[tid + o]; r1[tid] += r1[tid + o]; }
        __syncthreads();
    }
    if (tid == 0) {
        float bv = bias[co];
        g_act5[co]       = fmaxf(r0[0] + bv, 0.f);
        g_act5[512 + co] = fmaxf(r1[0] + bv, 0.f);
    }
}

// ---------------------------------------------------------------------------
// FC + reparameterization. grid (2), block (128).
// ---------------------------------------------------------------------------
__global__ void fc_reparam(const float* __restrict__ fcw, const float* __restrict__ fcb,
                           const float* __restrict__ eps, float* __restrict__ out_tail)
{
    int b = blockIdx.x, j = threadIdx.x;
    float mu = fcb[j], lv = fcb[j + 128];
    const float* xb = g_act5 + b * 512;
    for (int k = 0; k < 512; k++) {
        float xv = xb[k];
        mu += xv * fcw[k * 256 + j];
        lv += xv * fcw[k * 256 + j + 128];
    }
    out_tail[b * 128 + j] = mu;
    out_tail[256 + b * 128 + j] = lv;
    g_z[b * 128 + j] = mu + eps[b * 128 + j] * expf(0.5f * lv);
}

// ---------------------------------------------------------------------------
// deltas = z@dl_w+dl_b ; feats = relu(z@fl_w+fl_b)
// ---------------------------------------------------------------------------
__global__ void latent_kernel(const float* __restrict__ dlw, const float* __restrict__ dlb,
                              const float* __restrict__ flw, const float* __restrict__ flb)
{
    int idx = blockIdx.x * 256 + threadIdx.x;
    if (idx >= 2 * 50685) return;
    int b = idx / 50685;
    int c = idx - b * 50685;
    const float* zb = g_z + b * 128;
    if (c < 1533) {
        float s = dlb[c];
        for (int k = 0; k < 128; k++) s += zb[k] * dlw[k * 1533 + c];
        g_deltas[b * 1533 + c] = s;
    } else {
        int c2 = c - 1533;
        float s = flb[c2];
        for (int k = 0; k < 128; k++) s += zb[k] * flw[k * 49152 + c2];
        g_feats[b * 49152 + c2] = fmaxf(s, 0.f);
    }
}

// ---------------------------------------------------------------------------
// softmax(deltas) -> cumsum -> knots. 6 blocks (b*3+axis), 512 threads.
// ---------------------------------------------------------------------------
__global__ void knots_kernel()
{
    int pair = blockIdx.x;
    int t = threadIdx.x;
    __shared__ float red[512];
    __shared__ float sc[512];
    float v = (t < 511) ? g_deltas[pair * 511 + t] : -1e30f;
    red[t] = v; __syncthreads();
    for (int o = 256; o > 0; o >>= 1) {
        if (t < o) red[t] = fmaxf(red[t], red[t + o]);
        __syncthreads();
    }
    float mx = red[0]; __syncthreads();
    float e = (t < 511) ? expf(v - mx) : 0.f;
    red[t] = e; __syncthreads();
    for (int o = 256; o > 0; o >>= 1) {
        if (t < o) red[t] += red[t + o];
        __syncthreads();
    }
    float r = e / red[0];
    __syncthreads();
    sc[t] = r; __syncthreads();
    for (int o = 1; o < 512; o <<= 1) {
        float add = (t >= o) ? sc[t - o] : 0.f;
        __syncthreads();
        sc[t] += add;
        __syncthreads();
    }
    if (t < 511) g_knots[pair * 512 + t + 1] = sc[t];
    if (t == 0)  g_knots[pair * 512] = 0.f;
}

// ---------------------------------------------------------------------------
// Line tables: per (b,axis,gridpos) interpolate one 32-d feature row.
// ---------------------------------------------------------------------------
__global__ void ltab_kernel()
{
    int gidx = blockIdx.x;            // (b*3+axis)*96 + g
    int pair = gidx / 96;
    int g = gidx - pair * 96;
    float ua = (g + 0.5f) / 96.f;
    const float* kn = g_knots + pair * 512;
    int lo = 0, hi = 512;
    while (lo < hi) {
        int mid = (lo + hi) >> 1;
        if (kn[mid] <= ua) lo = mid + 1; else hi = mid;
    }
    int idx = min(max(lo - 1, 0), 510);
    float t0 = kn[idx], t1 = kn[idx + 1];
    float w = fminf(fmaxf((ua - t0) / (t1 - t0 + 1e-8f), 0.f), 1.f);
    int d = threadIdx.x;
    const float* f0 = g_feats + (pair * 512 + idx) * 32;
    g_ltab[gidx * 32 + d] = f0[d] * (1.f - w) + f0[32 + d] * w;
}

// ---------------------------------------------------------------------------
// Fused CP-product + decoder MLP, packed f32x2 with transposed W1 in smem.
// Per hidden unit j: one packed accumulator, 16 FMA2 over packed f-pairs
// (broadcast LDS.128). Live regs: f2[16] + 1 acc — no spill risk.
// grid (x=96, yq=4, b=2), 256 threads.
// ---------------------------------------------------------------------------
__global__ __launch_bounds__(256) void decode_kernel(
    const float* __restrict__ w1, const float* __restrict__ b1,
    const float* __restrict__ w2, const float* __restrict__ b2v,
    float* __restrict__ out)
{
    int x = blockIdx.x, yq = blockIdx.y, b = blockIdx.z;
    __shared__ __align__(16) float Wt[64][32];   // Wt[j][d] = w1[d*64+j]
    __shared__ float b1s[64];
    __shared__ float w2s[64];
    __shared__ float av[32];
    __shared__ float L1s[24 * 32];
    __shared__ float L2s[96 * 32];
    int tid = threadIdx.x;
    for (int i = tid; i < 2048; i += 256) {
        int d = i >> 6, j = i & 63;
        Wt[j][d] = w1[i];
    }
    if (tid < 64) { b1s[tid] = b1[tid]; w2s[tid] = w2[tid]; }
    if (tid < 32) av[tid] = g_ltab[((b * 3 + 0) * 96 + x) * 32 + tid];
    for (int i = tid; i < 768; i += 256)
        L1s[i] = g_ltab[((b * 3 + 1) * 96 + yq * 24) * 32 + i];
    for (int i = tid; i < 3072; i += 256)
        L2s[i] = g_ltab[((b * 3 + 2) * 96) * 32 + i];
    __syncthreads();

    float b2c = b2v[0];

    for (int p = tid; p < 2304; p += 256) {
        int y = p / 96;
        int z = p - y * 96;
        const float* l1 = &L1s[y * 32];
        const float* l2 = &L2s[z * 32];
        ull f2[16];
        #pragma unroll
        for (int q = 0; q < 16; q++) {
            float f0 = av[2 * q]     * l1[2 * q]     * l2[2 * q];
            float f1 = av[2 * q + 1] * l1[2 * q + 1] * l2[2 * q + 1];
            f2[q] = pk2(f0, f1);
        }
        float logit = b2c;
        #pragma unroll 1
        for (int j = 0; j < 64; j++) {
            const ull* wr = (const ull*)&Wt[j][0];
            ull acc = 0ull;
            #pragma unroll
            for (int q = 0; q < 16; q++) acc = fma2_(f2[q], wr[q], acc);
            float h0, h1;
            upk2(acc, h0, h1);
            float h = h0 + h1 + b1s[j];
            logit += fmaxf(h, 0.f) * w2s[j];
        }
        out[b * P3 + x * 9216 + (yq * 24 + y) * 96 + z] = logit;
    }
}

// ---------------------------------------------------------------------------
// Host launcher
// ---------------------------------------------------------------------------
extern "C" void kernel_launch(void* const* d_in, const int* in_sizes, int n_in,
                              void* d_out, int out_size)
{
    const float* occ  = (const float*)d_in[0];
    const float* eps  = (const float*)d_in[1];
    // d_in[2] = coords (regular grid; recomputed on device)
    const float* cw[6] = { (const float*)d_in[3], (const float*)d_in[5],
                           (const float*)d_in[7], (const float*)d_in[9],
                           (const float*)d_in[11], (const float*)d_in[13] };
    const float* cb[6] = { (const float*)d_in[4], (const float*)d_in[6],
                           (const float*)d_in[8], (const float*)d_in[10],
                           (const float*)d_in[12], (const float*)d_in[14] };
    const float* fc_w = (const float*)d_in[15];
    const float* fc_b = (const float*)d_in[16];
    const float* dl_w = (const float*)d_in[17];
    const float* dl_b = (const float*)d_in[18];
    const float* fl_w = (const float*)d_in[19];
    const float* fl_b = (const float*)d_in[20];
    const float* dw1  = (const float*)d_in[21];
    const float* db1  = (const float*)d_in[22];
    const float* dw2  = (const float*)d_in[23];
    const float* db2  = (const float*)d_in[24];
    float* out = (float*)d_out;

    float *pad_in, *act0, *act1, *act2, *act3, *act4, *accum;
    cudaGetSymbolAddress((void**)&pad_in, g_pad_in);
    cudaGetSymbolAddress((void**)&act0, g_act0);
    cudaGetSymbolAddress((void**)&act1, g_act1);
    cudaGetSymbolAddress((void**)&act2, g_act2);
    cudaGetSymbolAddress((void**)&act3, g_act3);
    cudaGetSymbolAddress((void**)&act4, g_act4);
    cudaGetSymbolAddress((void**)&accum, g_accum);

    pad_kernel<<<(2 * P3) / 256, 256>>>(occ);

    // layers 0..4 via implicit GEMM (L0 fused epilogue, others split-K)
    struct LCfg { int Cin, Sp, Sout, Cout, K, N, Nt, Mt, sk, Spn; };
    LCfg L[5] = {
        {  1, 98, 48,  32,    64, 221184, 3456, 1,  1, 50},
        { 32, 50, 24,  64,  2048,  27648,  432, 1,  2, 26},
        { 64, 26, 12, 128,  4096,   3456,   54, 2,  4, 14},
        {128, 14,  6, 256,  8192,    432,    7, 4, 16,  8},
        {256,  8,  3, 512, 16384,     54,    1, 8, 32,  5},
    };
    float* ins[5]  = { pad_in, act0, act1, act2, act3 };
    float* outs[5] = { act0, act1, act2, act3, act4 };

    for (int l = 0; l < 5; l++) {
        LCfg& c = L[l];
        int Npad = c.Nt * 64;
        if (c.sk > 1) {
            int cnt = c.Cout * Npad;
            zero_kernel<<<(cnt + 255) / 256, 256>>>(accum, cnt);
        }
        dim3 grid(c.Nt, c.Mt, c.sk);
        conv_gemm<<<grid, 256>>>(ins[l], cw[l], accum, cb[l], outs[l],
                                 c.Cin, c.Sp, c.Sout, c.Cout,
                                 c.K, c.N, Npad, c.K / c.sk, c.Spn);
        if (c.sk > 1) {
            int en = c.Cout * c.N;
            conv_epilogue<<<(en + 255) / 256, 256>>>(accum, cb[l], outs[l],
                                                     c.Cout, c.Sout, c.Spn,
                                                     c.N, Npad);
        }
    }

    // layer 5 matvec (N=2): gather col, then one block per output channel
    l5_xcol<<<256, 256>>>();
    l5_matvec<<<512, 256>>>(cw[5], cb[5]);

    fc_reparam<<<2, 128>>>(fc_w, fc_b, eps, out + OUT_MU_OFF);
    latent_kernel<<<(2 * 50685 + 255) / 256, 256>>>(dl_w, dl_b, fl_w, fl_b);
    knots_kernel<<<6, 512>>>();
    ltab_kernel<<<576, 32>>>();
    decode_kernel<<<dim3(96, 4, 2), 256>>>(dw1, db1, dw2, db2, out);
}

// round 12
// speedup vs baseline: 1.2143x; 1.2143x over previous
#include <cuda_runtime.h>
#include <math.h>

// ---------------------------------------------------------------------------
// Static device scratch (zero-initialized at module load; halos stay zero).
// ---------------------------------------------------------------------------
__device__ float g_pad_in[1882384];   // [2][1][98][98][98]
__device__ float g_act0[8000000];     // [2][32][50][50][50]
__device__ float g_act1[2249728];     // [2][64][26][26][26]
__device__ float g_act2[702464];      // [2][128][14][14][14]
__device__ float g_act3[262144];      // [2][256][8][8][8]
__device__ float g_act4[128000];      // [2][512][5][5][5]
__device__ float g_act5[1024];        // [2][512] flat
__device__ float g_accum[7077888];    // conv split-K accumulator / l5 xcol scratch
__device__ float g_z[256];            // [2][128]
__device__ float g_deltas[3066];      // [2][3][511]
__device__ float g_knots[3072];       // [2][3][512]
__device__ float g_feats[98304];      // [2][3][512][32]
__device__ float g_ltab[18432];       // [2][3][96][32]

#define P3 884736       // 96^3
#define OUT_MU_OFF 1769472

typedef unsigned long long ull;

__device__ __forceinline__ ull pk2(float x, float y) {
    ull r; asm("mov.b64 %0, {%1,%2};" : "=l"(r) : "f"(x), "f"(y)); return r;
}
__device__ __forceinline__ void upk2(ull v, float& x, float& y) {
    asm("mov.b64 {%0,%1}, %2;" : "=f"(x), "=f"(y) : "l"(v));
}
__device__ __forceinline__ ull fma2_(ull a, ull b, ull c) {
    ull d; asm("fma.rn.f32x2 %0, %1, %2, %3;" : "=l"(d) : "l"(a), "l"(b), "l"(c)); return d;
}

// ---------------------------------------------------------------------------
// Pad occ [2,1,96,96,96] into [2,1,98,98,98] (halo already zero).
// ---------------------------------------------------------------------------
__global__ void pad_kernel(const float* __restrict__ occ) {
    int idx = blockIdx.x * 256 + threadIdx.x;
    if (idx >= 2 * P3) return;
    int b = idx / P3;
    int r = idx - b * P3;
    int d = r / 9216;
    int h = (r / 96) % 96;
    int w = r % 96;
    g_pad_in[b * 941192 + (d + 1) * 9604 + (h + 1) * 98 + (w + 1)] = occ[idx];
}

__global__ void zero_kernel(float* __restrict__ p, int n) {
    int i = blockIdx.x * 256 + threadIdx.x;
    if (i < n) p[i] = 0.f;
}

// ---------------------------------------------------------------------------
// Implicit-GEMM conv: C[co, n] = sum_k W[co,k] * col[k,n]
// 64(M) x 128(N) x 16(K) tiles, 256 threads (ty 0-7 x tx 0-31),
// micro-tile 8(M) x 4(N) with M-PACKED accumulator pairs:
//   c2[i][j] = (C[m0+2i][n], C[m0+2i+1][n]) — A pairs load natively as
//   broadcast LDS.128 from plain As; B is one LDS.128 + 4 pk2 dups.
// Mainloop per kk: 3 LDS + 4 MOV + 16 FFMA2  -> FMA-bound.
// grid.z = split-K (atomicAdd); gridDim.z==1 fuses bias+ReLU+scatter.
// ---------------------------------------------------------------------------
__global__ __launch_bounds__(256) void conv_gemm(
    const float* __restrict__ inp, const float* __restrict__ wgt,
    float* __restrict__ accum, const float* __restrict__ bias,
    float* __restrict__ fout,
    int Cin, int Sp, int Sout, int Cout, int K, int N, int Npad, int Kchunk,
    int Spn)
{
    __shared__ __align__(16) float As[2][16][68];    // plain A[k][m]
    __shared__ __align__(16) float Bs[2][16][132];   // B[k][n], stride 132
    __shared__ int baseN[128];
    int tid = threadIdx.x;
    int bx = blockIdx.x, by = blockIdx.y;
    int Sp2 = Sp * Sp, Sp3 = Sp2 * Sp;

    if (tid < 128) {
        int n = bx * 128 + tid;
        int base = 0;
        if (n < N) {
            int s2 = Sout * Sout, s3 = s2 * Sout;
            int b = n / s3; int rem = n - b * s3;
            int od = rem / s2; rem -= od * s2;
            int oh = rem / Sout; int ow = rem - oh * Sout;
            base = b * Cin * Sp3 + 2 * od * Sp2 + 2 * oh * Sp + 2 * ow;
        }
        baseN[tid] = base;
    }
    __syncthreads();

    int tx = tid & 31;            // 0..31 -> cols n0..n0+3
    int ty = tid >> 5;            // 0..7  -> rows m0..m0+7
    int n0 = tx * 4;
    int m0 = ty * 8;

    int m_ld = tid >> 2;          // A loader: row (co), 0..63
    int kq   = (tid & 3) * 4;     // A loader: 4 consecutive k
    int kk_b = tid >> 4;          // B loader: k row, 0..15
    int nb8  = (tid & 15) * 8;    // B loader: 8 n cols
    int k0 = blockIdx.z * Kchunk;

    int coA = by * 64 + m_ld;
    bool mval = (coA < Cout);
    const float* wrowp = wgt + (long long)coA * K + k0 + kq;
    int bbs[8];
    #pragma unroll
    for (int i = 0; i < 8; i++) bbs[i] = baseN[nb8 + i];

    ull c2[4][4];   // [m-pair][col]
    #pragma unroll
    for (int i = 0; i < 4; i++)
        #pragma unroll
        for (int j = 0; j < 4; j++) c2[i][j] = 0ull;

    int nst = Kchunk >> 4;
    float ar[4], br[8];

    // prologue: stage 0
    {
        #pragma unroll
        for (int i = 0; i < 4; i++) ar[i] = mval ? wrowp[i] : 0.f;
        int kg = k0 + kk_b;
        int ci = kg >> 6, rr = kg & 63;
        int off = ci * Sp3 + (rr >> 4) * Sp2 + ((rr >> 2) & 3) * Sp + (rr & 3);
        #pragma unroll
        for (int i = 0; i < 8; i++) br[i] = inp[bbs[i] + off];
        #pragma unroll
        for (int i = 0; i < 4; i++) As[0][kq + i][m_ld] = ar[i];
        *(float4*)&Bs[0][kk_b][nb8]     = make_float4(br[0], br[1], br[2], br[3]);
        *(float4*)&Bs[0][kk_b][nb8 + 4] = make_float4(br[4], br[5], br[6], br[7]);
    }
    __syncthreads();

    for (int t = 0; t < nst; t++) {
        int cur = t & 1;
        bool more = (t + 1 < nst);
        if (more) {
            const float* wp = wrowp + (t + 1) * 16;
            #pragma unroll
            for (int i = 0; i < 4; i++) ar[i] = mval ? wp[i] : 0.f;
            int kg = k0 + (t + 1) * 16 + kk_b;
            int ci = kg >> 6, rr = kg & 63;
            int off = ci * Sp3 + (rr >> 4) * Sp2 + ((rr >> 2) & 3) * Sp + (rr & 3);
            #pragma unroll
            for (int i = 0; i < 8; i++) br[i] = inp[bbs[i] + off];
        }
        #pragma unroll
        for (int kk = 0; kk < 16; kk++) {
            // A pairs: broadcast LDS.128 (uniform address per warp)
            double2 apq0 = *(const double2*)&As[cur][kk][m0];      // (A[m0],A[m0+1]),(A[m0+2],A[m0+3])
            double2 apq1 = *(const double2*)&As[cur][kk][m0 + 4];
            // B: 4 distinct cols, one LDS.128
            float4 bv = *(const float4*)&Bs[cur][kk][n0];
            ull ap0 = __double_as_longlong(apq0.x);
            ull ap1 = __double_as_longlong(apq0.y);
            ull ap2 = __double_as_longlong(apq1.x);
            ull ap3 = __double_as_longlong(apq1.y);
            ull b0 = pk2(bv.x, bv.x);
            ull b1 = pk2(bv.y, bv.y);
            ull b2 = pk2(bv.z, bv.z);
            ull b3 = pk2(bv.w, bv.w);
            c2[0][0] = fma2_(ap0, b0, c2[0][0]);
            c2[0][1] = fma2_(ap0, b1, c2[0][1]);
            c2[0][2] = fma2_(ap0, b2, c2[0][2]);
            c2[0][3] = fma2_(ap0, b3, c2[0][3]);
            c2[1][0] = fma2_(ap1, b0, c2[1][0]);
            c2[1][1] = fma2_(ap1, b1, c2[1][1]);
            c2[1][2] = fma2_(ap1, b2, c2[1][2]);
            c2[1][3] = fma2_(ap1, b3, c2[1][3]);
            c2[2][0] = fma2_(ap2, b0, c2[2][0]);
            c2[2][1] = fma2_(ap2, b1, c2[2][1]);
            c2[2][2] = fma2_(ap2, b2, c2[2][2]);
            c2[2][3] = fma2_(ap2, b3, c2[2][3]);
            c2[3][0] = fma2_(ap3, b0, c2[3][0]);
            c2[3][1] = fma2_(ap3, b1, c2[3][1]);
            c2[3][2] = fma2_(ap3, b2, c2[3][2]);
            c2[3][3] = fma2_(ap3, b3, c2[3][3]);
        }
        if (more) {
            int nx = cur ^ 1;
            #pragma unroll
            for (int i = 0; i < 4; i++) As[nx][kq + i][m_ld] = ar[i];
            *(float4*)&Bs[nx][kk_b][nb8]     = make_float4(br[0], br[1], br[2], br[3]);
            *(float4*)&Bs[nx][kk_b][nb8 + 4] = make_float4(br[4], br[5], br[6], br[7]);
        }
        __syncthreads();
    }

    // unpack: rows m0+2i, m0+2i+1
    float c[8][4];
    #pragma unroll
    for (int i = 0; i < 4; i++)
        #pragma unroll
        for (int j = 0; j < 4; j++)
            upk2(c2[i][j], c[2 * i][j], c[2 * i + 1][j]);

    if (gridDim.z == 1) {
        // fused bias + ReLU + scatter to padded output
        int Spn2 = Spn * Spn;
        int s2 = Sout * Sout, s3 = s2 * Sout;
        #pragma unroll
        for (int i = 0; i < 8; i++) {
            int co = by * 64 + m0 + i;
            if (co >= Cout) continue;
            float bv = bias[co];
            #pragma unroll
            for (int j = 0; j < 4; j++) {
                int n = bx * 128 + n0 + j;
                if (n < N) {
                    int b = n / s3; int rem = n - b * s3;
                    int od = rem / s2; rem -= od * s2;
                    int oh = rem / Sout; int ow = rem - oh * Sout;
                    float v = fmaxf(c[i][j] + bv, 0.f);
                    fout[((b * Cout + co) * Spn + od + 1) * Spn2 + (oh + 1) * Spn + (ow + 1)] = v;
                }
            }
        }
    } else {
        #pragma unroll
        for (int i = 0; i < 8; i++) {
            int co = by * 64 + m0 + i;
            if (co >= Cout) continue;
            #pragma unroll
            for (int j = 0; j < 4; j++) {
                int n = bx * 128 + n0 + j;
                if (n < N) atomicAdd(&accum[co * Npad + n], c[i][j]);
            }
        }
    }
}

// ---------------------------------------------------------------------------
// Epilogue for split-K layers: bias + ReLU + scatter into next padded buffer.
// ---------------------------------------------------------------------------
__global__ void conv_epilogue(
    const float* __restrict__ accum, const float* __restrict__ bias,
    float* __restrict__ outp,
    int Cout, int Sout, int Spn, int N, int Npad)
{
    int idx = blockIdx.x * 256 + threadIdx.x;
    if (idx >= Cout * N) return;
    int m = idx / N;
    int n = idx - m * N;
    float v = fmaxf(accum[m * Npad + n] + bias[m], 0.f);
    int s2 = Sout * Sout, s3 = s2 * Sout;
    int b = n / s3; int rem = n - b * s3;
    int od = rem / s2; rem -= od * s2;
    int oh = rem / Sout; int ow = rem - oh * Sout;
    int Spn2 = Spn * Spn;
    outp[((b * Cout + m) * Spn + od + 1) * Spn2 + (oh + 1) * Spn + (ow + 1)] = v;
}

// ---------------------------------------------------------------------------
// Layer 5: gather col vector (coalesced scratch), then matvec over 32768.
// ---------------------------------------------------------------------------
__global__ void l5_xcol() {
    int idx = blockIdx.x * 256 + threadIdx.x;   // 2*32768
    if (idx >= 65536) return;
    int b = idx >> 15;
    int k = idx & 32767;
    int ci = k >> 6, rr = k & 63;
    int off = ci * 125 + (rr >> 4) * 25 + ((rr >> 2) & 3) * 5 + (rr & 3);
    g_accum[idx] = g_act4[b * 64000 + off];
}

__global__ __launch_bounds__(256) void l5_matvec(
    const float* __restrict__ wgt, const float* __restrict__ bias)
{
    int co = blockIdx.x;
    int tid = threadIdx.x;
    const float* w = wgt + (long long)co * 32768;
    float s0 = 0.f, s1 = 0.f;
    for (int k = tid; k < 32768; k += 256) {
        float wv = w[k];
        s0 += wv * g_accum[k];
        s1 += wv * g_accum[32768 + k];
    }
    __shared__ float r0[256], r1[256];
    r0[tid] = s0; r1[tid] = s1;
    __syncthreads();
    for (int o = 128; o > 0; o >>= 1) {
        if (tid < o) { r0[tid] += r0[tid + o]; r1[tid] += r1[tid + o]; }
        __syncthreads();
    }
    if (tid == 0) {
        float bv = bias[co];
        g_act5[co]       = fmaxf(r0[0] + bv, 0.f);
        g_act5[512 + co] = fmaxf(r1[0] + bv, 0.f);
    }
}

// ---------------------------------------------------------------------------
// FC + reparameterization. grid (2), block (128).
// ---------------------------------------------------------------------------
__global__ void fc_reparam(const float* __restrict__ fcw, const float* __restrict__ fcb,
                           const float* __restrict__ eps, float* __restrict__ out_tail)
{
    int b = blockIdx.x, j = threadIdx.x;
    float mu = fcb[j], lv = fcb[j + 128];
    const float* xb = g_act5 + b * 512;
    for (int k = 0; k < 512; k++) {
        float xv = xb[k];
        mu += xv * fcw[k * 256 + j];
        lv += xv * fcw[k * 256 + j + 128];
    }
    out_tail[b * 128 + j] = mu;
    out_tail[256 + b * 128 + j] = lv;
    g_z[b * 128 + j] = mu + eps[b * 128 + j] * expf(0.5f * lv);
}

// ---------------------------------------------------------------------------
// deltas = z@dl_w+dl_b ; feats = relu(z@fl_w+fl_b)
// ---------------------------------------------------------------------------
__global__ void latent_kernel(const float* __restrict__ dlw, const float* __restrict__ dlb,
                              const float* __restrict__ flw, const float* __restrict__ flb)
{
    int idx = blockIdx.x * 256 + threadIdx.x;
    if (idx >= 2 * 50685) return;
    int b = idx / 50685;
    int c = idx - b * 50685;
    const float* zb = g_z + b * 128;
    if (c < 1533) {
        float s = dlb[c];
        for (int k = 0; k < 128; k++) s += zb[k] * dlw[k * 1533 + c];
        g_deltas[b * 1533 + c] = s;
    } else {
        int c2 = c - 1533;
        float s = flb[c2];
        for (int k = 0; k < 128; k++) s += zb[k] * flw[k * 49152 + c2];
        g_feats[b * 49152 + c2] = fmaxf(s, 0.f);
    }
}

// ---------------------------------------------------------------------------
// softmax(deltas) -> cumsum -> knots. 6 blocks (b*3+axis), 512 threads.
// ---------------------------------------------------------------------------
__global__ void knots_kernel()
{
    int pair = blockIdx.x;
    int t = threadIdx.x;
    __shared__ float red[512];
    __shared__ float sc[512];
    float v = (t < 511) ? g_deltas[pair * 511 + t] : -1e30f;
    red[t] = v; __syncthreads();
    for (int o = 256; o > 0; o >>= 1) {
        if (t < o) red[t] = fmaxf(red[t], red[t + o]);
        __syncthreads();
    }
    float mx = red[0]; __syncthreads();
    float e = (t < 511) ? expf(v - mx) : 0.f;
    red[t] = e; __syncthreads();
    for (int o = 256; o > 0; o >>= 1) {
        if (t < o) red[t] += red[t + o];
        __syncthreads();
    }
    float r = e / red[0];
    __syncthreads();
    sc[t] = r; __syncthreads();
    for (int o = 1; o < 512; o <<= 1) {
        float add = (t >= o) ? sc[t - o] : 0.f;
        __syncthreads();
        sc[t] += add;
        __syncthreads();
    }
    if (t < 511) g_knots[pair * 512 + t + 1] = sc[t];
    if (t == 0)  g_knots[pair * 512] = 0.f;
}

// ---------------------------------------------------------------------------
// Line tables: per (b,axis,gridpos) interpolate one 32-d feature row.
// ---------------------------------------------------------------------------
__global__ void ltab_kernel()
{
    int gidx = blockIdx.x;            // (b*3+axis)*96 + g
    int pair = gidx / 96;
    int g = gidx - pair * 96;
    float ua = (g + 0.5f) / 96.f;
    const float* kn = g_knots + pair * 512;
    int lo = 0, hi = 512;
    while (lo < hi) {
        int mid = (lo + hi) >> 1;
        if (kn[mid] <= ua) lo = mid + 1; else hi = mid;
    }
    int idx = min(max(lo - 1, 0), 510);
    float t0 = kn[idx], t1 = kn[idx + 1];
    float w = fminf(fmaxf((ua - t0) / (t1 - t0 + 1e-8f), 0.f), 1.f);
    int d = threadIdx.x;
    const float* f0 = g_feats + (pair * 512 + idx) * 32;
    g_ltab[gidx * 32 + d] = f0[d] * (1.f - w) + f0[32 + d] * w;
}

// ---------------------------------------------------------------------------
// Fused CP-product + decoder MLP, packed f32x2 with transposed W1 in smem.
// Line tables padded to STRIDE 33 — the stride-32 layout put every thread
// of a warp on the same bank (32-way conflict on each L2s/L1s read).
// grid (x=96, yq=4, b=2), 256 threads.
// ---------------------------------------------------------------------------
__global__ __launch_bounds__(256) void decode_kernel(
    const float* __restrict__ w1, const float* __restrict__ b1,
    const float* __restrict__ w2, const float* __restrict__ b2v,
    float* __restrict__ out)
{
    int x = blockIdx.x, yq = blockIdx.y, b = blockIdx.z;
    __shared__ __align__(16) float Wt[64][32];   // Wt[j][d] = w1[d*64+j]
    __shared__ float b1s[64];
    __shared__ float w2s[64];
    __shared__ float av[32];
    __shared__ float L1s[24 * 33];               // stride 33: conflict-free
    __shared__ float L2s[96 * 33];
    int tid = threadIdx.x;
    for (int i = tid; i < 2048; i += 256) {
        int d = i >> 6, j = i & 63;
        Wt[j][d] = w1[i];
    }
    if (tid < 64) { b1s[tid] = b1[tid]; w2s[tid] = w2[tid]; }
    if (tid < 32) av[tid] = g_ltab[((b * 3 + 0) * 96 + x) * 32 + tid];
    for (int i = tid; i < 768; i += 256) {
        int r = i >> 5, d = i & 31;
        L1s[r * 33 + d] = g_ltab[((b * 3 + 1) * 96 + yq * 24) * 32 + i];
    }
    for (int i = tid; i < 3072; i += 256) {
        int r = i >> 5, d = i & 31;
        L2s[r * 33 + d] = g_ltab[((b * 3 + 2) * 96) * 32 + i];
    }
    __syncthreads();

    float b2c = b2v[0];

    for (int p = tid; p < 2304; p += 256) {
        int y = p / 96;
        int z = p - y * 96;
        const float* l1 = &L1s[y * 33];
        const float* l2 = &L2s[z * 33];
        ull f2[16];
        #pragma unroll
        for (int q = 0; q < 16; q++) {
            float f0 = av[2 * q]     * l1[2 * q]     * l2[2 * q];
            float f1 = av[2 * q + 1] * l1[2 * q + 1] * l2[2 * q + 1];
            f2[q] = pk2(f0, f1);
        }
        float logit = b2c;
        #pragma unroll 1
        for (int j = 0; j < 64; j++) {
            const ull* wr = (const ull*)&Wt[j][0];
            ull acc = 0ull;
            #pragma unroll
            for (int q = 0; q < 16; q++) acc = fma2_(f2[q], wr[q], acc);
            float h0, h1;
            upk2(acc, h0, h1);
            float h = h0 + h1 + b1s[j];
            logit += fmaxf(h, 0.f) * w2s[j];
        }
        out[b * P3 + x * 9216 + (yq * 24 + y) * 96 + z] = logit;
    }
}

// ---------------------------------------------------------------------------
// Host launcher
// ---------------------------------------------------------------------------
extern "C" void kernel_launch(void* const* d_in, const int* in_sizes, int n_in,
                              void* d_out, int out_size)
{
    const float* occ  = (const float*)d_in[0];
    const float* eps  = (const float*)d_in[1];
    // d_in[2] = coords (regular grid; recomputed on device)
    const float* cw[6] = { (const float*)d_in[3], (const float*)d_in[5],
                           (const float*)d_in[7], (const float*)d_in[9],
                           (const float*)d_in[11], (const float*)d_in[13] };
    const float* cb[6] = { (const float*)d_in[4], (const float*)d_in[6],
                           (const float*)d_in[8], (const float*)d_in[10],
                           (const float*)d_in[12], (const float*)d_in[14] };
    const float* fc_w = (const float*)d_in[15];
    const float* fc_b = (const float*)d_in[16];
    const float* dl_w = (const float*)d_in[17];
    const float* dl_b = (const float*)d_in[18];
    const float* fl_w = (const float*)d_in[19];
    const float* fl_b = (const float*)d_in[20];
    const float* dw1  = (const float*)d_in[21];
    const float* db1  = (const float*)d_in[22];
    const float* dw2  = (const float*)d_in[23];
    const float* db2  = (const float*)d_in[24];
    float* out = (float*)d_out;

    float *pad_in, *act0, *act1, *act2, *act3, *act4, *accum;
    cudaGetSymbolAddress((void**)&pad_in, g_pad_in);
    cudaGetSymbolAddress((void**)&act0, g_act0);
    cudaGetSymbolAddress((void**)&act1, g_act1);
    cudaGetSymbolAddress((void**)&act2, g_act2);
    cudaGetSymbolAddress((void**)&act3, g_act3);
    cudaGetSymbolAddress((void**)&act4, g_act4);
    cudaGetSymbolAddress((void**)&accum, g_accum);

    pad_kernel<<<(2 * P3) / 256, 256>>>(occ);

    // layers 0..4 via implicit GEMM (L0 fused epilogue, others split-K)
    // N-tile is now 128: Nt = ceil(N/128), Mt = ceil(Cout/64).
    struct LCfg { int Cin, Sp, Sout, Cout, K, N, Nt, Mt, sk, Spn; };
    LCfg L[5] = {
        {  1, 98, 48,  32,    64, 221184, 1728, 1,  1, 50},
        { 32, 50, 24,  64,  2048,  27648,  216, 1,  2, 26},
        { 64, 26, 12, 128,  4096,   3456,   27, 2,  4, 14},
        {128, 14,  6, 256,  8192,    432,    4, 4,  8,  8},
        {256,  8,  3, 512, 16384,     54,    1, 8, 16,  5},
    };
    float* ins[5]  = { pad_in, act0, act1, act2, act3 };
    float* outs[5] = { act0, act1, act2, act3, act4 };

    for (int l = 0; l < 5; l++) {
        LCfg& c = L[l];
        int Npad = c.Nt * 128;
        if (c.sk > 1) {
            int cnt = c.Cout * Npad;
            zero_kernel<<<(cnt + 255) / 256, 256>>>(accum, cnt);
        }
        dim3 grid(c.Nt, c.Mt, c.sk);
        conv_gemm<<<grid, 256>>>(ins[l], cw[l], accum, cb[l], outs[l],
                                 c.Cin, c.Sp, c.Sout, c.Cout,
                                 c.K, c.N, Npad, c.K / c.sk, c.Spn);
        if (c.sk > 1) {
            int en = c.Cout * c.N;
            conv_epilogue<<<(en + 255) / 256, 256>>>(accum, cb[l], outs[l],
                                                     c.Cout, c.Sout, c.Spn,
                                                     c.N, Npad);
        }
    }

    // layer 5 matvec (N=2): gather col, then one block per output channel
    l5_xcol<<<256, 256>>>();
    l5_matvec<<<512, 256>>>(cw[5], cb[5]);

    fc_reparam<<<2, 128>>>(fc_w, fc_b, eps, out + OUT_MU_OFF);
    latent_kernel<<<(2 * 50685 + 255) / 256, 256>>>(dl_w, dl_b, fl_w, fl_b);
    knots_kernel<<<6, 512>>>();
    ltab_kernel<<<576, 32>>>();
    decode_kernel<<<dim3(96, 4, 2), 256>>>(dw1, db1, dw2, db2, out);
}